// round 2
// baseline (speedup 1.0000x reference)
#include <cuda_runtime.h>
#include <math.h>

#define NTHREADS 128
#define HID 64
#define GRID 304

// ---------------- SMEM layout (float offsets) ----------------
#define OFF_SW1 0
#define OFF_SB1 448
#define OFF_SW2 512
#define OFF_SB2 4608
#define OFF_SW3 4672
#define OFF_SB3 4736
#define OFF_AW1 4740
#define OFF_AB1 5188
#define OFF_AW2 5252
#define OFF_AB2 9348
#define OFF_AW3 9412
#define OFF_AB3 9476
#define OFF_FW1 9480
#define OFF_FB1 9864
#define OFF_FW2 9928
#define OFF_FB2 14024
#define OFF_FW3 14088
#define OFF_FB3 14152
#define OFF_RW1 14156
#define OFF_RB1 14476
#define OFF_RW2 14540
#define OFF_RB2 18636
#define OFF_RW3 18700
#define OFF_RB3 18892
#define OFF_IMEAN 18896
#define OFF_ISTD  18904
#define OFF_TMEAN 18912
#define OFF_TSTD  18916
#define OFF_ACT   18920
#define SMEM_FLOATS (OFF_ACT + NTHREADS * HID)
#define SMEM_BYTES (SMEM_FLOATS * 4)

struct KParams {
    const float* in[30];
    float* out;
    int B;
};

// Copy table for inputs 2..29 -> smem
__device__ __constant__ int kCnt[28] = {
    5, 5, 3, 3,
    448, 64, 4096, 64, 64, 1,
    448, 64, 4096, 64, 64, 1,
    384, 64, 4096, 64, 64, 1,
    320, 64, 4096, 64, 192, 3   // rW3 is (64,3) = 192 floats (was 64: BUG)
};
__device__ __constant__ int kOff[28] = {
    OFF_IMEAN, OFF_ISTD, OFF_TMEAN, OFF_TSTD,
    OFF_SW1, OFF_SB1, OFF_SW2, OFF_SB2, OFF_SW3, OFF_SB3,
    OFF_AW1, OFF_AB1, OFF_AW2, OFF_AB2, OFF_AW3, OFF_AB3,
    OFF_FW1, OFF_FB1, OFF_FW2, OFF_FB2, OFF_FW3, OFF_FB3,
    OFF_RW1, OFF_RB1, OFF_RW2, OFF_RB2, OFF_RW3, OFF_RB3
};

// accurate-enough fast tanh: abs error ~1e-7, MUFU: 1x EX2 + 1x RCP
__device__ __forceinline__ float fast_tanhf(float x) {
    float ax = fabsf(x);
    float e  = __expf(2.0f * ax);
    float t  = 1.0f - __fdividef(2.0f, e + 1.0f);
    return (x < 0.0f) ? -t : t;
}

__device__ __forceinline__ float softplusf(float x) {
    float t = __expf(-fabsf(x));
    return fmaxf(x, 0.0f) + __logf(1.0f + t);
}

// One full MLP: DIN -> 64 (tanh) -> 64 (tanh) -> DOUT
// x: DIN values in registers. act: per-thread smem scratch (stride NTHREADS).
template <int DIN, int DOUT>
__device__ __forceinline__ void run_mlp(
    const float* __restrict__ x,
    const float* __restrict__ sm,
    int oW1, int ob1, int oW2, int ob2, int oW3, int ob3,
    float* __restrict__ act,
    float* __restrict__ outv)
{
    float acc[HID];

    // layer 1: DIN -> 64
    {
        const float4* b4 = (const float4*)(sm + ob1);
#pragma unroll
        for (int j = 0; j < 16; j++) {
            float4 b = b4[j];
            acc[4*j+0] = b.x; acc[4*j+1] = b.y; acc[4*j+2] = b.z; acc[4*j+3] = b.w;
        }
    }
#pragma unroll
    for (int i = 0; i < DIN; i++) {
        float xi = x[i];
        const float4* w4 = (const float4*)(sm + oW1 + i * HID);
#pragma unroll
        for (int j = 0; j < 16; j++) {
            float4 w = w4[j];
            acc[4*j+0] = fmaf(xi, w.x, acc[4*j+0]);
            acc[4*j+1] = fmaf(xi, w.y, acc[4*j+1]);
            acc[4*j+2] = fmaf(xi, w.z, acc[4*j+2]);
            acc[4*j+3] = fmaf(xi, w.w, acc[4*j+3]);
        }
    }
    // tanh -> smem activations (conflict-free: lanes contiguous)
#pragma unroll
    for (int j = 0; j < HID; j++) act[j * NTHREADS] = fast_tanhf(acc[j]);

    // layer 2: 64 -> 64
    {
        const float4* b4 = (const float4*)(sm + ob2);
#pragma unroll
        for (int j = 0; j < 16; j++) {
            float4 b = b4[j];
            acc[4*j+0] = b.x; acc[4*j+1] = b.y; acc[4*j+2] = b.z; acc[4*j+3] = b.w;
        }
    }
#pragma unroll 4
    for (int i = 0; i < HID; i++) {
        float hi = act[i * NTHREADS];
        const float4* w4 = (const float4*)(sm + oW2 + i * HID);
#pragma unroll
        for (int j = 0; j < 16; j++) {
            float4 w = w4[j];
            acc[4*j+0] = fmaf(hi, w.x, acc[4*j+0]);
            acc[4*j+1] = fmaf(hi, w.y, acc[4*j+1]);
            acc[4*j+2] = fmaf(hi, w.z, acc[4*j+2]);
            acc[4*j+3] = fmaf(hi, w.w, acc[4*j+3]);
        }
    }
#pragma unroll
    for (int j = 0; j < HID; j++) acc[j] = fast_tanhf(acc[j]);

    // layer 3: 64 -> DOUT (broadcast LDS for W3)
#pragma unroll
    for (int o = 0; o < DOUT; o++) outv[o] = sm[ob3 + o];
#pragma unroll
    for (int j = 0; j < HID; j++) {
        float hj = acc[j];
#pragma unroll
        for (int o = 0; o < DOUT; o++)
            outv[o] = fmaf(hj, sm[oW3 + j * DOUT + o], outv[o]);
    }
}

extern __shared__ float sm[];

__global__ void __launch_bounds__(NTHREADS)
fused_mlp_kernel(KParams p)
{
    const int tid = threadIdx.x;

    // Stage all weights + norm params into SMEM once per CTA.
    for (int a = 0; a < 28; a++) {
        const float* src = p.in[a + 2];
        const int n = kCnt[a];
        const int o = kOff[a];
        for (int k = tid; k < n; k += NTHREADS) sm[o + k] = src[k];
    }
    __syncthreads();

    float* act = sm + OFF_ACT + tid;
    const float* xd0 = p.in[0];
    const float* utr = p.in[1];
    const int Btot = p.B;
    const int stride = gridDim.x * NTHREADS;

    for (int row = blockIdx.x * NTHREADS + tid; row < Btot; row += stride) {
        float x0 = xd0[row * 3 + 0];
        float x1 = xd0[row * 3 + 1];
        float x2 = xd0[row * 3 + 2];
        float x3 = utr[row * 2 + 0];
        float x4 = utr[row * 2 + 1];

        float vx    = __fdividef(x0 - sm[OFF_IMEAN + 0], sm[OFF_ISTD + 0]);
        float vy    = __fdividef(x1 - sm[OFF_IMEAN + 1], sm[OFF_ISTD + 1]);
        float wz    = __fdividef(x2 - sm[OFF_IMEAN + 2], sm[OFF_ISTD + 2]);
        float vel   = __fdividef(x3 - sm[OFF_IMEAN + 3], sm[OFF_ISTD + 3]);
        float delta = __fdividef(x4 - sm[OFF_IMEAN + 4], sm[OFF_ISTD + 4]);

        float vmag  = sqrtf(fmaf(vx, vx, fmaf(vy, vy, 1e-8f)));
        float vsign = (vx > 0.0f) ? 1.0f : ((vx < 0.0f) ? -1.0f : 0.0f);

        // steer MLP
        float si[7] = {delta, vel, vx, vy, wz, vmag, vsign};
        float so;
        run_mlp<7, 1>(si, sm, OFF_SW1, OFF_SB1, OFF_SW2, OFF_SB2, OFF_SW3, OFF_SB3, act, &so);
        float d_steer = 0.5f * fast_tanhf(so);

        // acc MLP
        float ai[7] = {vel, delta, vx, vmag, vsign, vy, wz};
        float ao;
        run_mlp<7, 1>(ai, sm, OFF_AW1, OFF_AB1, OFF_AW2, OFF_AB2, OFF_AW3, OFF_AB3, act, &ao);
        float d_acc = 0.5f * fast_tanhf(ao);

        float ue0 = vel + d_acc;
        float ue1 = delta + d_steer;

        // friction MLP
        float fi[6] = {vx, vy, wz, ue0, ue1, 0.02f};
        float fo;
        run_mlp<6, 1>(fi, sm, OFF_FW1, OFF_FB1, OFF_FW2, OFF_FB2, OFF_FW3, OFF_FB3, act, &fo);
        float friction_k = 1.0f + softplusf(fo);

        // residual MLP
        float ri[5] = {vx, vy, wz, ue0, ue1};
        float ro[3];
        run_mlp<5, 3>(ri, sm, OFF_RW1, OFF_RB1, OFF_RW2, OFF_RB2, OFF_RW3, OFF_RB3, act, ro);

        float r0 = fmaf(ro[0], sm[OFF_TSTD + 0], sm[OFF_TMEAN + 0]);
        float r1 = fmaf(ro[1], sm[OFF_TSTD + 1], sm[OFF_TMEAN + 1]);
        float r2 = fmaf(ro[2], sm[OFF_TSTD + 2], sm[OFF_TMEAN + 2]);

        float u0 = fmaf(ue0, sm[OFF_ISTD + 3], sm[OFF_IMEAN + 3]);
        float u1 = fmaf(ue1, sm[OFF_ISTD + 4], sm[OFF_IMEAN + 4]);

        // outputs: [ut_eff_raw (B,2)] [friction_k (B,1)] [residual (B,3)]
        p.out[row * 2 + 0] = u0;
        p.out[row * 2 + 1] = u1;
        p.out[2 * Btot + row] = friction_k;
        p.out[3 * Btot + row * 3 + 0] = r0;
        p.out[3 * Btot + row * 3 + 1] = r1;
        p.out[3 * Btot + row * 3 + 2] = r2;
    }
}

extern "C" void kernel_launch(void* const* d_in, const int* in_sizes, int n_in,
                              void* d_out, int out_size)
{
    KParams p;
    for (int i = 0; i < 30; i++) p.in[i] = (const float*)d_in[i];
    p.out = (float*)d_out;
    p.B = in_sizes[0] / 3;

    cudaFuncSetAttribute(fused_mlp_kernel,
                         cudaFuncAttributeMaxDynamicSharedMemorySize, SMEM_BYTES);
    fused_mlp_kernel<<<GRID, NTHREADS, SMEM_BYTES>>>(p);
}

// round 3
// speedup vs baseline: 1.5500x; 1.5500x over previous
#include <cuda_runtime.h>
#include <math.h>

#define NTHREADS 128
#define HID 64
#define GRID 444   // 3 CTAs/SM * 148 SMs

typedef unsigned long long u64;

// ---------------- SMEM layout (float offsets) ----------------
#define OFF_SW1 0
#define OFF_SB1 448
#define OFF_SW2 512
#define OFF_SB2 4608
#define OFF_SW3 4672
#define OFF_SB3 4736
#define OFF_AW1 4740
#define OFF_AB1 5188
#define OFF_AW2 5252
#define OFF_AB2 9348
#define OFF_AW3 9412
#define OFF_AB3 9476
#define OFF_FW1 9480
#define OFF_FB1 9864
#define OFF_FW2 9928
#define OFF_FB2 14024
#define OFF_FW3 14088
#define OFF_FB3 14152
#define OFF_RW1 14156
#define OFF_RB1 14476
#define OFF_RW2 14540
#define OFF_RB2 18636
#define OFF_RW3 18700
#define OFF_RB3 18892
#define OFF_IMEAN 18896
#define OFF_ISTD  18904
#define OFF_TMEAN 18912
#define OFF_TSTD  18916
#define SMEM_FLOATS 18920
#define SMEM_BYTES (SMEM_FLOATS * 4)

struct KParams {
    const float* in[30];
    float* out;
    int B;
};

__device__ __constant__ int kCnt[28] = {
    5, 5, 3, 3,
    448, 64, 4096, 64, 64, 1,
    448, 64, 4096, 64, 64, 1,
    384, 64, 4096, 64, 64, 1,
    320, 64, 4096, 64, 192, 3
};
__device__ __constant__ int kOff[28] = {
    OFF_IMEAN, OFF_ISTD, OFF_TMEAN, OFF_TSTD,
    OFF_SW1, OFF_SB1, OFF_SW2, OFF_SB2, OFF_SW3, OFF_SB3,
    OFF_AW1, OFF_AB1, OFF_AW2, OFF_AB2, OFF_AW3, OFF_AB3,
    OFF_FW1, OFF_FB1, OFF_FW2, OFF_FB2, OFF_FW3, OFF_FB3,
    OFF_RW1, OFF_RB1, OFF_RW2, OFF_RB2, OFF_RW3, OFF_RB3
};

// ---------------- packed f32x2 helpers ----------------
__device__ __forceinline__ u64 dup2(float a) {
    u64 r; asm("mov.b64 %0, {%1, %1};" : "=l"(r) : "f"(a)); return r;
}
__device__ __forceinline__ u64 ffma2(u64 a, u64 b, u64 c) {
    u64 d; asm("fma.rn.f32x2 %0, %1, %2, %3;" : "=l"(d) : "l"(a), "l"(b), "l"(c)); return d;
}
__device__ __forceinline__ float2 unpk2(u64 a) {
    float2 f; asm("mov.b64 {%0, %1}, %2;" : "=f"(f.x), "=f"(f.y) : "l"(a)); return f;
}

// accurate fast tanh: abs error ~1e-7, 2 MUFU (EX2 + RCP)
__device__ __forceinline__ float fast_tanhf(float x) {
    float ax = fabsf(x);
    float e  = __expf(2.0f * ax);
    float t  = 1.0f - __fdividef(2.0f, e + 1.0f);
    return (x < 0.0f) ? -t : t;
}

__device__ __forceinline__ float softplusf(float x) {
    float t = __expf(-fabsf(x));
    return fmaxf(x, 0.0f) + __logf(1.0f + t);
}

// One full MLP: DIN -> 64 (tanh) -> 64 (tanh) -> DOUT.
// All hidden state in registers; weights from smem via packed f32x2.
template <int DIN, int DOUT>
__device__ __forceinline__ void run_mlp(
    const float* __restrict__ x,
    const float* __restrict__ sm,
    int oW1, int ob1, int oW2, int ob2, int oW3, int ob3,
    float* __restrict__ outv)
{
    u64 acc[32];
    float h[HID];

    // ---- layer 1: DIN -> 64 ----
    {
        const u64* b2 = (const u64*)(sm + ob1);
#pragma unroll
        for (int j = 0; j < 32; j++) acc[j] = b2[j];
    }
#pragma unroll
    for (int i = 0; i < DIN; i++) {
        u64 xi = dup2(x[i]);
        const u64* w = (const u64*)(sm + oW1 + i * HID);
#pragma unroll
        for (int j = 0; j < 32; j++) acc[j] = ffma2(xi, w[j], acc[j]);
    }
#pragma unroll
    for (int j = 0; j < 32; j++) {
        float2 v = unpk2(acc[j]);
        h[2*j]   = fast_tanhf(v.x);
        h[2*j+1] = fast_tanhf(v.y);
    }

    // ---- layer 2: 64 -> 64 ----
    {
        const u64* b2 = (const u64*)(sm + ob2);
#pragma unroll
        for (int j = 0; j < 32; j++) acc[j] = b2[j];
    }
#pragma unroll
    for (int i = 0; i < HID; i++) {
        u64 hi = dup2(h[i]);
        const u64* w = (const u64*)(sm + oW2 + i * HID);
#pragma unroll
        for (int j = 0; j < 32; j++) acc[j] = ffma2(hi, w[j], acc[j]);
    }
#pragma unroll
    for (int j = 0; j < 32; j++) {
        float2 v = unpk2(acc[j]);
        h[2*j]   = fast_tanhf(v.x);
        h[2*j+1] = fast_tanhf(v.y);
    }

    // ---- layer 3: 64 -> DOUT ----
#pragma unroll
    for (int o = 0; o < DOUT; o++) outv[o] = sm[ob3 + o];
#pragma unroll
    for (int j = 0; j < HID; j++) {
        float hj = h[j];
#pragma unroll
        for (int o = 0; o < DOUT; o++)
            outv[o] = fmaf(hj, sm[oW3 + j * DOUT + o], outv[o]);
    }
}

extern __shared__ float sm[];

__global__ void __launch_bounds__(NTHREADS, 3)
fused_mlp_kernel(KParams p)
{
    const int tid = threadIdx.x;

    // Stage all weights + norm params into SMEM once per CTA.
    for (int a = 0; a < 28; a++) {
        const float* src = p.in[a + 2];
        const int n = kCnt[a];
        const int o = kOff[a];
        for (int k = tid; k < n; k += NTHREADS) sm[o + k] = src[k];
    }
    __syncthreads();

    const float* xd0 = p.in[0];
    const float* utr = p.in[1];
    const int Btot = p.B;
    const int stride = gridDim.x * NTHREADS;

    for (int row = blockIdx.x * NTHREADS + tid; row < Btot; row += stride) {
        float x0 = xd0[row * 3 + 0];
        float x1 = xd0[row * 3 + 1];
        float x2 = xd0[row * 3 + 2];
        float x3 = utr[row * 2 + 0];
        float x4 = utr[row * 2 + 1];

        float vx    = __fdividef(x0 - sm[OFF_IMEAN + 0], sm[OFF_ISTD + 0]);
        float vy    = __fdividef(x1 - sm[OFF_IMEAN + 1], sm[OFF_ISTD + 1]);
        float wz    = __fdividef(x2 - sm[OFF_IMEAN + 2], sm[OFF_ISTD + 2]);
        float vel   = __fdividef(x3 - sm[OFF_IMEAN + 3], sm[OFF_ISTD + 3]);
        float delta = __fdividef(x4 - sm[OFF_IMEAN + 4], sm[OFF_ISTD + 4]);

        float vmag  = sqrtf(fmaf(vx, vx, fmaf(vy, vy, 1e-8f)));
        float vsign = (vx > 0.0f) ? 1.0f : ((vx < 0.0f) ? -1.0f : 0.0f);

        // steer MLP
        float si[7] = {delta, vel, vx, vy, wz, vmag, vsign};
        float so;
        run_mlp<7, 1>(si, sm, OFF_SW1, OFF_SB1, OFF_SW2, OFF_SB2, OFF_SW3, OFF_SB3, &so);
        float d_steer = 0.5f * fast_tanhf(so);

        // acc MLP
        float ai[7] = {vel, delta, vx, vmag, vsign, vy, wz};
        float ao;
        run_mlp<7, 1>(ai, sm, OFF_AW1, OFF_AB1, OFF_AW2, OFF_AB2, OFF_AW3, OFF_AB3, &ao);
        float d_acc = 0.5f * fast_tanhf(ao);

        float ue0 = vel + d_acc;
        float ue1 = delta + d_steer;

        // friction MLP
        float fi[6] = {vx, vy, wz, ue0, ue1, 0.02f};
        float fo;
        run_mlp<6, 1>(fi, sm, OFF_FW1, OFF_FB1, OFF_FW2, OFF_FB2, OFF_FW3, OFF_FB3, &fo);
        float friction_k = 1.0f + softplusf(fo);

        // residual MLP
        float ri[5] = {vx, vy, wz, ue0, ue1};
        float ro[3];
        run_mlp<5, 3>(ri, sm, OFF_RW1, OFF_RB1, OFF_RW2, OFF_RB2, OFF_RW3, OFF_RB3, ro);

        float r0 = fmaf(ro[0], sm[OFF_TSTD + 0], sm[OFF_TMEAN + 0]);
        float r1 = fmaf(ro[1], sm[OFF_TSTD + 1], sm[OFF_TMEAN + 1]);
        float r2 = fmaf(ro[2], sm[OFF_TSTD + 2], sm[OFF_TMEAN + 2]);

        float u0 = fmaf(ue0, sm[OFF_ISTD + 3], sm[OFF_IMEAN + 3]);
        float u1 = fmaf(ue1, sm[OFF_ISTD + 4], sm[OFF_IMEAN + 4]);

        // outputs: [ut_eff_raw (B,2)] [friction_k (B,1)] [residual (B,3)]
        p.out[row * 2 + 0] = u0;
        p.out[row * 2 + 1] = u1;
        p.out[2 * Btot + row] = friction_k;
        p.out[3 * Btot + row * 3 + 0] = r0;
        p.out[3 * Btot + row * 3 + 1] = r1;
        p.out[3 * Btot + row * 3 + 2] = r2;
    }
}

extern "C" void kernel_launch(void* const* d_in, const int* in_sizes, int n_in,
                              void* d_out, int out_size)
{
    KParams p;
    for (int i = 0; i < 30; i++) p.in[i] = (const float*)d_in[i];
    p.out = (float*)d_out;
    p.B = in_sizes[0] / 3;

    cudaFuncSetAttribute(fused_mlp_kernel,
                         cudaFuncAttributeMaxDynamicSharedMemorySize, SMEM_BYTES);
    fused_mlp_kernel<<<GRID, NTHREADS, SMEM_BYTES>>>(p);
}